// round 4
// baseline (speedup 1.0000x reference)
#include <cuda_runtime.h>
#include <math.h>
#include <stdint.h>

#define NN      32768
#define KTOT    (3 * NN)
#define NPART   296
#define NTILES  (NN / 16)
#define EPSF    1e-5f

__device__ __constant__ float c_TPN = 0.022097086912079608f;  // 1/sqrt(16*128)
__device__ __constant__ float c_ISV = 0.08838834764831845f;   // 1/sqrt(128)

// ---------------- static device scratch ----------------
__device__ float g_part[NPART][128 * 128];
__device__ float g_G[128 * 128];
__device__ float g_Wc1[128 * 128];
__device__ float g_A[3][128 * 128];
__device__ float g_T[3][128 * 128];
__device__ float g_c[128];

// ---------------------------------------------------------------------------
// Gram: G = Y^T Y with packed f32x2 FMAs (verified in R1).
// ---------------------------------------------------------------------------
__global__ void __launch_bounds__(256, 2)
k_gram(const float* __restrict__ feat, const float* __restrict__ times) {
    __shared__ __align__(16) float B[48][132];
    unsigned long long acc[8][4];
#pragma unroll
    for (int i = 0; i < 8; i++)
#pragma unroll
        for (int j = 0; j < 4; j++) acc[i][j] = 0ull;

    const int tid = threadIdx.x;
    const int ty = tid >> 4;
    const int tx = tid & 15;

    for (int tile = blockIdx.x; tile < NTILES; tile += NPART) {
        __syncthreads();
        const int node0 = tile * 16;
#pragma unroll
        for (int i = 0; i < 6; i++) {
            const int f = tid + 256 * i;
            const int r = f / 96;
            const int q = f - r * 96;
            const int n = node0 + r;
            const float4 val =
                *(const float4*)(feat + (size_t)n * 512 + 128 + 4 * q);
            const float tm = __ldg(times + n);
            const int j = 4 * q;
            B[r * 3 + (j    ) % 3][(j    ) / 3] = tm * val.x;
            B[r * 3 + (j + 1) % 3][(j + 1) / 3] = tm * val.y;
            B[r * 3 + (j + 2) % 3][(j + 2) / 3] = tm * val.z;
            B[r * 3 + (j + 3) % 3][(j + 3) / 3] = tm * val.w;
        }
        __syncthreads();
#pragma unroll 2
        for (int k = 0; k < 48; k++) {
            const float4 a0 = *(const float4*)&B[k][ty * 8];
            const float4 a1 = *(const float4*)&B[k][ty * 8 + 4];
            const ulonglong2 q0 = *(const ulonglong2*)&B[k][tx * 8];
            const ulonglong2 q1 = *(const ulonglong2*)&B[k][tx * 8 + 4];
            const unsigned long long bp[4] = {q0.x, q0.y, q1.x, q1.y};
            const float a[8] = {a0.x, a0.y, a0.z, a0.w,
                                a1.x, a1.y, a1.z, a1.w};
#pragma unroll
            for (int i = 0; i < 8; i++) {
                unsigned long long ap;
                const unsigned int au = __float_as_uint(a[i]);
                asm("mov.b64 %0, {%1,%1};" : "=l"(ap) : "r"(au));
#pragma unroll
                for (int j = 0; j < 4; j++)
                    asm("fma.rn.f32x2 %0, %1, %2, %0;"
                        : "+l"(acc[i][j]) : "l"(ap), "l"(bp[j]));
            }
        }
    }

    float* outp = g_part[blockIdx.x];
#pragma unroll
    for (int i = 0; i < 8; i++)
#pragma unroll
        for (int j = 0; j < 4; j++) {
            unsigned int lo, hi;
            asm("mov.b64 {%0,%1}, %2;" : "=r"(lo), "=r"(hi) : "l"(acc[i][j]));
            outp[(ty * 8 + i) * 128 + tx * 8 + 2 * j]     = __uint_as_float(lo);
            outp[(ty * 8 + i) * 128 + tx * 8 + 2 * j + 1] = __uint_as_float(hi);
        }
}

__global__ void k_greduce() {
    const int i = blockIdx.x * blockDim.x + threadIdx.x;  // 0..16383
    float s = 0.f;
#pragma unroll 8
    for (int p = 0; p < NPART; p++) s += g_part[p][i];
    g_G[i] = s;
}

// ---------------------------------------------------------------------------
// Fused chain: one cluster of 8 CTAs, each owns 16 rows of every 128x128
// matrix. Cross-CTA visibility via global + threadfence + barrier.cluster.
// ---------------------------------------------------------------------------
__device__ __forceinline__ void cfence_sync() {
    __threadfence();
    asm volatile("barrier.cluster.arrive.aligned;" ::: "memory");
    asm volatile("barrier.cluster.wait.aligned;" ::: "memory");
}

__device__ __forceinline__ void gemm_rows(
    const float* __restrict__ Arows,  // 16x128 (global, own rows)
    const float* __restrict__ Bg,     // 128x128 (global)
    float* __restrict__ Crows,        // 16x128 (global, own rows)
    float scale, const float* dvec,   // per-column scale on A (or nullptr)
    float (*As)[132], float (*Bs)[68], int tid) {
#pragma unroll
    for (int i = 0; i < 2; i++) {
        const int e = tid + 256 * i;       // 0..511 float4 slots
        const int r = e >> 5;
        const int c4 = e & 31;
        float4 v = *(const float4*)(Arows + r * 128 + c4 * 4);
        if (dvec) {
            v.x *= dvec[c4 * 4 + 0];
            v.y *= dvec[c4 * 4 + 1];
            v.z *= dvec[c4 * 4 + 2];
            v.w *= dvec[c4 * 4 + 3];
        }
        *(float4*)&As[r][c4 * 4] = v;
    }
    const int lane = tid & 31, wid = tid >> 5;
    const int rr = (wid & 3) * 4 + (lane >> 3);   // 0..15
    const int cc = (wid >> 2) * 8 + (lane & 7);   // 0..15 (float4 col in half)
#pragma unroll
    for (int cb = 0; cb < 2; cb++) {
        __syncthreads();  // As ready / previous half's compute done
#pragma unroll
        for (int i = 0; i < 8; i++) {
            const int idx = tid + 256 * i;  // 0..2047 float4 slots
            const int w = idx >> 4;
            const int c4 = idx & 15;
            float4 v = *(const float4*)(Bg + w * 128 + cb * 64 + c4 * 4);
            *(float4*)&Bs[w][c4 * 4] = v;
        }
        __syncthreads();
        float a0 = 0.f, a1 = 0.f, a2 = 0.f, a3 = 0.f;
#pragma unroll 8
        for (int w = 0; w < 128; w++) {
            const float a = As[rr][w];
            const float4 b = *(const float4*)&Bs[w][cc * 4];
            a0 = fmaf(a, b.x, a0);
            a1 = fmaf(a, b.y, a1);
            a2 = fmaf(a, b.z, a2);
            a3 = fmaf(a, b.w, a3);
        }
        float4 o = make_float4(a0 * scale, a1 * scale, a2 * scale, a3 * scale);
        *(float4*)(Crows + rr * 128 + cb * 64 + cc * 4) = o;
    }
}

__global__ void __cluster_dims__(8, 1, 1) __launch_bounds__(256)
k_chain(const float* __restrict__ W_time, const float* __restrict__ W_tp1,
        const float* __restrict__ Wv, const float* __restrict__ gamma_v,
        const float* __restrict__ W_r) {
    __shared__ float As[16][132];
    __shared__ float Bs[128][68];
    __shared__ float dvec[128];
    __shared__ float red[256];
    const int tid = threadIdx.x;
    const int rb = blockIdx.x;
    const int r0 = rb * 16;

    // Wc1 rows [r0, r0+16): Wc1[v,o] = tpn * sum_u wt[u] * Wtp1[u,v,o]
#pragma unroll
    for (int i = 0; i < 8; i++) {
        const int e = tid + 256 * i;  // 0..2047
        const int v = r0 + (e >> 7);
        const int o = e & 127;
        float acc = 0.f;
#pragma unroll
        for (int u = 0; u < 16; u++)
            acc = fmaf(__ldg(W_time + u), __ldg(W_tp1 + u * 16384 + v * 128 + o),
                       acc);
        g_Wc1[v * 128 + o] = acc * c_TPN;
    }
    __syncthreads();

    const float* Aprev = g_Wc1;
    for (int s = 0; s < 3; s++) {
        // A_s = (A_prev ⊙ d_{s-1}) @ Wv[s] * isv
        gemm_rows(Aprev + r0 * 128, Wv + s * 16384, g_A[s] + r0 * 128, c_ISV,
                  (s > 0) ? dvec : (const float*)0, As, Bs, tid);
        cfence_sync();
        // T_s = G @ A_s
        gemm_rows(g_G + r0 * 128, g_A[s], g_T[s] + r0 * 128, 1.0f,
                  (const float*)0, As, Bs, tid);
        cfence_sync();
        // fn (duplicated per CTA): dvec[o] = gamma*rsqrt(mean(A.T)+eps)
        {
            const int o = tid & 127, h = tid >> 7;
            const float* A = g_A[s];
            const float* T = g_T[s];
            float sf = 0.f;
#pragma unroll 8
            for (int v = h * 64; v < h * 64 + 64; v++)
                sf = fmaf(A[v * 128 + o], T[v * 128 + o], sf);
            red[tid] = sf;
            __syncthreads();
            if (h == 0)
                dvec[o] = __ldg(gamma_v + s * 128 + o) *
                          rsqrtf((red[o] + red[128 + o]) * (1.0f / (float)KTOT) +
                                 EPSF);
            __syncthreads();
        }
        Aprev = g_A[s];
    }
    // c[v] = isv * sum_o A2[v,o] * d2[o] * W_r[o]   (own 16 rows)
    if (tid < 16) {
        const int v = r0 + tid;
        float acc = 0.f;
#pragma unroll 8
        for (int o = 0; o < 128; o++)
            acc = fmaf(g_A[2][v * 128 + o], dvec[o] * __ldg(W_r + o), acc);
        g_c[v] = acc * c_ISV;
    }
}

// out[n,m] = time_n * sum_v x_v[n,v,m] * c[v]   (one warp per node)
__global__ void k_out(const float* __restrict__ feat,
                      const float* __restrict__ times,
                      float* __restrict__ out) {
    const int gw = (blockIdx.x * blockDim.x + threadIdx.x) >> 5;
    const int lane = threadIdx.x & 31;
    if (gw >= NN) return;
    const float4* p = (const float4*)(feat + (size_t)gw * 512 + 128);
    float s0 = 0.f, s1 = 0.f, s2 = 0.f;
#pragma unroll
    for (int i = 0; i < 3; i++) {
        const int f4 = lane + 32 * i;
        const float4 x = p[f4];
        const int j = 4 * f4;
        const float comp[4] = {x.x, x.y, x.z, x.w};
#pragma unroll
        for (int e = 0; e < 4; e++) {
            const int jj = j + e;
            const float pr = comp[e] * g_c[jj / 3];
            const int m = jj % 3;
            s0 += (m == 0) ? pr : 0.f;
            s1 += (m == 1) ? pr : 0.f;
            s2 += (m == 2) ? pr : 0.f;
        }
    }
#pragma unroll
    for (int off = 16; off > 0; off >>= 1) {
        s0 += __shfl_xor_sync(0xffffffffu, s0, off);
        s1 += __shfl_xor_sync(0xffffffffu, s1, off);
        s2 += __shfl_xor_sync(0xffffffffu, s2, off);
    }
    if (lane == 0) {
        const float tm = times[gw];
        out[gw * 3 + 0] = tm * s0;
        out[gw * 3 + 1] = tm * s1;
        out[gw * 3 + 2] = tm * s2;
    }
}

// ---------------------------------------------------------------------------
extern "C" void kernel_launch(void* const* d_in, const int* in_sizes, int n_in,
                              void* d_out, int out_size) {
    const float* feat    = (const float*)d_in[0];
    const float* times   = (const float*)d_in[1];
    const float* W_time  = (const float*)d_in[2];
    const float* W_tp1   = (const float*)d_in[4];
    const float* Wv      = (const float*)d_in[6];
    const float* gamma_v = (const float*)d_in[9];
    const float* W_r     = (const float*)d_in[10];
    float* out = (float*)d_out;

    k_gram<<<NPART, 256>>>(feat, times);
    k_greduce<<<64, 256>>>();
    k_chain<<<8, 256>>>(W_time, W_tp1, Wv, gamma_v, W_r);
    k_out<<<(NN * 32) / 256, 256>>>(feat, times, out);
}